// round 1
// baseline (speedup 1.0000x reference)
#include <cuda_runtime.h>
#include <math.h>

#define BB 8
#define TT 4096
#define TP1 4097
#define DD 1024
#define KK 1024
#define MM (BB*TT)

// ---- scratch (device globals; no allocation allowed) ----
__device__ float g_logf[(size_t)MM * DD];        // log_f  [B,T,D]
__device__ float g_lv  [(size_t)BB * TP1 * DD];  // log_values [B,T+1,D]
__device__ float g_as  [(size_t)BB * TP1 * DD];  // a_star [B,T+1,D]

// ---- math helpers ----
__device__ __forceinline__ float sp(float x) {          // softplus, stable
    return fmaxf(x, 0.0f) + log1pf(expf(-fabsf(x)));
}
__device__ __forceinline__ float log_g(float x) {       // where(x>=0, log(x+0.5), -softplus(-x))
    return (x >= 0.0f) ? logf(x + 0.5f) : -sp(-x);
}
__device__ __forceinline__ float2 unpack64(unsigned long long u) {
    float2 r;
    asm("mov.b64 {%0, %1}, %2;" : "=f"(r.x), "=f"(r.y) : "l"(u));
    return r;
}

// =====================================================================
// Kernel 1: fused triple GEMM  z{i,f,h}[m,o] = sum_k x[m,k]*W{i,f,h}[o,k] + b
// plus epilogue producing log_f and log_values.
// BM=128, BN=64, BK=16, 256 threads, per-thread 8x4 microtile x 3 outputs,
// inner loop in packed fma.rn.f32x2 (2 FMA/instr).
// =====================================================================
#define BM 128
#define BN 64
#define BK 16
#define TM 8
#define TN 4

__global__ void __launch_bounds__(256, 1) gemm3_kernel(
    const float* __restrict__ x,
    const float* __restrict__ Wi, const float* __restrict__ bi,
    const float* __restrict__ Wf, const float* __restrict__ bf,
    const float* __restrict__ Wh, const float* __restrict__ bh)
{
    __shared__ __align__(16) float As[BK][BM];
    __shared__ __align__(16) float Ws[3][BK][BN];

    const int tid = threadIdx.x;
    const int n0 = blockIdx.x * BN;   // x-dim = N blocks (16) -> x tiles reused across wave
    const int m0 = blockIdx.y * BM;   // y-dim = M blocks (256)
    const int tx = tid & 15;          // 0..15 -> col frag
    const int ty = tid >> 4;          // 0..15 -> row frag

    unsigned long long acc[3][TM][TN / 2];
    #pragma unroll
    for (int mat = 0; mat < 3; mat++)
        #pragma unroll
        for (int i = 0; i < TM; i++)
            #pragma unroll
            for (int jp = 0; jp < TN / 2; jp++)
                acc[mat][i][jp] = 0ull;

    const float* Wp0 = Wi; const float* Wp1 = Wf; const float* Wp2 = Wh;

    for (int k0 = 0; k0 < KK; k0 += BK) {
        // ---- load A tile (128x16), stored transposed As[k][m] ----
        #pragma unroll
        for (int i = 0; i < 2; i++) {
            int li  = tid * 2 + i;       // 0..511
            int row = li >> 2;           // 0..127
            int cg  = li & 3;            // 0..3 (group of 4 k)
            float4 v = *(const float4*)(x + (size_t)(m0 + row) * KK + k0 + cg * 4);
            As[cg * 4 + 0][row] = v.x;
            As[cg * 4 + 1][row] = v.y;
            As[cg * 4 + 2][row] = v.z;
            As[cg * 4 + 3][row] = v.w;
        }
        // ---- load 3 W tiles (64x16 each), transposed Ws[mat][k][o] ----
        {
            int row = tid >> 2;          // 0..63
            int cg  = tid & 3;
            size_t off = (size_t)(n0 + row) * KK + k0 + cg * 4;
            float4 v0 = *(const float4*)(Wp0 + off);
            float4 v1 = *(const float4*)(Wp1 + off);
            float4 v2 = *(const float4*)(Wp2 + off);
            Ws[0][cg*4+0][row] = v0.x; Ws[0][cg*4+1][row] = v0.y;
            Ws[0][cg*4+2][row] = v0.z; Ws[0][cg*4+3][row] = v0.w;
            Ws[1][cg*4+0][row] = v1.x; Ws[1][cg*4+1][row] = v1.y;
            Ws[1][cg*4+2][row] = v1.z; Ws[1][cg*4+3][row] = v1.w;
            Ws[2][cg*4+0][row] = v2.x; Ws[2][cg*4+1][row] = v2.y;
            Ws[2][cg*4+2][row] = v2.z; Ws[2][cg*4+3][row] = v2.w;
        }
        __syncthreads();

        #pragma unroll
        for (int k = 0; k < BK; k++) {
            float4 av0 = *(const float4*)&As[k][ty * TM];
            float4 av1 = *(const float4*)&As[k][ty * TM + 4];
            unsigned long long ap[TM];
            asm("mov.b64 %0, {%1, %1};" : "=l"(ap[0]) : "f"(av0.x));
            asm("mov.b64 %0, {%1, %1};" : "=l"(ap[1]) : "f"(av0.y));
            asm("mov.b64 %0, {%1, %1};" : "=l"(ap[2]) : "f"(av0.z));
            asm("mov.b64 %0, {%1, %1};" : "=l"(ap[3]) : "f"(av0.w));
            asm("mov.b64 %0, {%1, %1};" : "=l"(ap[4]) : "f"(av1.x));
            asm("mov.b64 %0, {%1, %1};" : "=l"(ap[5]) : "f"(av1.y));
            asm("mov.b64 %0, {%1, %1};" : "=l"(ap[6]) : "f"(av1.z));
            asm("mov.b64 %0, {%1, %1};" : "=l"(ap[7]) : "f"(av1.w));

            #pragma unroll
            for (int mat = 0; mat < 3; mat++) {
                ulonglong2 bb = *(const ulonglong2*)&Ws[mat][k][tx * TN];
                #pragma unroll
                for (int i = 0; i < TM; i++) {
                    asm("fma.rn.f32x2 %0, %1, %2, %0;"
                        : "+l"(acc[mat][i][0]) : "l"(ap[i]), "l"(bb.x));
                    asm("fma.rn.f32x2 %0, %1, %2, %0;"
                        : "+l"(acc[mat][i][1]) : "l"(ap[i]), "l"(bb.y));
                }
            }
        }
        __syncthreads();
    }

    // ---- epilogue: gate math, write log_f and log_values ----
    const int row_base = m0 + ty * TM;
    const int col_base = n0 + tx * TN;
    float biav[TN], bfav[TN], bhav[TN];
    #pragma unroll
    for (int j = 0; j < TN; j++) {
        biav[j] = bi[col_base + j];
        bfav[j] = bf[col_base + j];
        bhav[j] = bh[col_base + j];
    }

    #pragma unroll
    for (int i = 0; i < TM; i++) {
        int row = row_base + i;
        int b   = row >> 12;                           // T = 4096
        size_t o_logf = (size_t)row * DD;
        size_t o_lv   = (size_t)(row + b + 1) * DD;    // (b*TP1 + t + 1)*D
        #pragma unroll
        for (int jp = 0; jp < TN / 2; jp++) {
            float2 fi = unpack64(acc[0][i][jp]);
            float2 ff = unpack64(acc[1][i][jp]);
            float2 fh = unpack64(acc[2][i][jp]);
            #pragma unroll
            for (int h = 0; h < 2; h++) {
                int j  = jp * 2 + h;
                float zi = (h ? fi.y : fi.x) + biav[j];
                float zf = (h ? ff.y : ff.x) + bfav[j];
                float zh = (h ? fh.y : fh.x) + bhav[j];
                float diff  = sp(-zf) - sp(-zi);
                float lf    = -sp(diff);
                float li    = -sp(-diff);
                float lv    = li + log_g(zh);
                int col = col_base + j;
                g_logf[o_logf + col] = lf;
                g_lv[o_lv + col]     = lv;
            }
        }
    }
}

// =====================================================================
// Kernel 0: log_values[:,0,:] = log_g(h_0)
// =====================================================================
__global__ void h0_kernel(const float* __restrict__ h0) {
    int i = blockIdx.x * 256 + threadIdx.x;  // < B*D = 8192
    int b = i >> 10;
    int d = i & (DD - 1);
    g_lv[(size_t)b * TP1 * DD + d] = log_g(h0[i]);
}

// =====================================================================
// Kernel 2: a_star[b,0,:] = 0 ; a_star[b,t+1,:] = cumsum_d(log_f[b,t,:])
// one 256-thread block per output row, block-wide inclusive scan of 1024
// =====================================================================
__global__ void __launch_bounds__(256) cumsum_kernel() {
    int r = blockIdx.x;              // 0 .. B*TP1-1
    int b = r / TP1;
    int t = r - b * TP1;
    int tid = threadIdx.x;
    float4* dst = (float4*)(g_as + (size_t)r * DD);

    if (t == 0) {
        dst[tid] = make_float4(0.f, 0.f, 0.f, 0.f);
        return;
    }
    const float4* src = (const float4*)(g_logf + (size_t)(b * TT + t - 1) * DD);
    float4 v = src[tid];
    v.y += v.x; v.z += v.y; v.w += v.z;
    float tsum = v.w;

    int lane = tid & 31, warp = tid >> 5;
    #pragma unroll
    for (int off = 1; off < 32; off <<= 1) {
        float n = __shfl_up_sync(0xffffffffu, tsum, off);
        if (lane >= off) tsum += n;
    }
    __shared__ float wsum[8];
    if (lane == 31) wsum[warp] = tsum;
    __syncthreads();
    float prev = tsum - v.w;             // exclusive within warp
    for (int w = 0; w < warp; w++) prev += wsum[w];
    v.x += prev; v.y += prev; v.z += prev; v.w += prev;
    dst[tid] = v;
}

// =====================================================================
// Kernel 3: streaming logcumsumexp over time; out = exp(a_star + log_h).
// One thread per (b,d); warp = 32 consecutive d -> fully coalesced.
// =====================================================================
__global__ void __launch_bounds__(256) scan_kernel(float* __restrict__ out) {
    int g = blockIdx.x * 256 + threadIdx.x;   // < B*D = 8192
    int b = g >> 10;
    int d = g & (DD - 1);
    size_t base = (size_t)b * TP1 * DD + d;

    float m = -INFINITY;
    float s = 0.0f;
    for (int t = 0; t < TP1; t++) {
        size_t idx = base + (size_t)t * DD;
        float a  = g_as[idx];
        float v  = g_lv[idx] - a;
        float mn = fmaxf(m, v);
        s = s * expf(m - mn) + expf(v - mn);
        m = mn;
        out[idx] = expf(a + m + logf(s));
    }
}

// =====================================================================
extern "C" void kernel_launch(void* const* d_in, const int* in_sizes, int n_in,
                              void* d_out, int out_size)
{
    const float* x  = (const float*)d_in[0];
    const float* h0 = (const float*)d_in[1];
    const float* Wi = (const float*)d_in[2];
    const float* bi = (const float*)d_in[3];
    const float* Wf = (const float*)d_in[4];
    const float* bf = (const float*)d_in[5];
    const float* Wh = (const float*)d_in[6];
    const float* bh = (const float*)d_in[7];
    float* out = (float*)d_out;
    (void)in_sizes; (void)n_in; (void)out_size;

    h0_kernel<<<(BB * DD) / 256, 256>>>(h0);
    gemm3_kernel<<<dim3(DD / BN, MM / BM), 256>>>(x, Wi, bi, Wf, bf, Wh, bh);
    cumsum_kernel<<<BB * TP1, 256>>>();
    scan_kernel<<<(BB * DD) / 256, 256>>>(out);
}

// round 5
// speedup vs baseline: 2.0920x; 2.0920x over previous
#include <cuda_runtime.h>
#include <cuda_bf16.h>
#include <math.h>
#include <stdint.h>

#define BB 8
#define TT 4096
#define TP1 4097
#define DD 1024
#define KK 1024
#define MM (BB*TT)
#define NP 3072

// ---------------- scratch (device globals) ----------------
// bf16 operands, pre-swizzled SW128 tiles:
//  x tiles: [mt 0..255][kc 0..15] -> 128 rows x 128B = 16384 B contiguous
//  w tiles: [nt 0..15 ][kc 0..15] -> 192 rows x 128B = 24576 B contiguous
//  w row within tile: r = ((d>>3)&7)*24 + mat*8 + (d&7)   (8-feature interleave)
__device__ __align__(16) unsigned char g_xh[(size_t)MM * KK * 2];
__device__ __align__(16) unsigned char g_xl[(size_t)MM * KK * 2];
__device__ __align__(16) unsigned char g_wh[(size_t)NP * KK * 2];
__device__ __align__(16) unsigned char g_wl[(size_t)NP * KK * 2];

__device__ float g_logf[(size_t)MM * DD];        // log_f [B,T,D]
__device__ float g_lv  [(size_t)BB * TP1 * DD];  // log_values [B,T+1,D]
__device__ float g_as  [(size_t)BB * TP1 * DD];  // a_star [B,T+1,D]

// ---------------- math helpers ----------------
__device__ __forceinline__ float sp(float x) {          // stable softplus
    return fmaxf(x, 0.0f) + log1pf(expf(-fabsf(x)));
}
__device__ __forceinline__ float log_g(float x) {
    return (x >= 0.0f) ? logf(x + 0.5f) : -sp(-x);
}

// ---------------- PTX helpers ----------------
__device__ __forceinline__ uint32_t smem_to_u32(const void* p) {
    uint32_t a;
    asm("{ .reg .u64 t; cvta.to.shared.u64 t, %1; cvt.u32.u64 %0, t; }"
        : "=r"(a) : "l"(p));
    return a;
}

#define MBARRIER_INIT(addr, cnt) \
    asm volatile("mbarrier.init.shared.b64 [%0], %1;" :: "r"((uint32_t)(addr)), "r"((uint32_t)(cnt)) : "memory")
#define MBARRIER_INVAL(addr) \
    asm volatile("mbarrier.inval.shared.b64 [%0];" :: "r"((uint32_t)(addr)) : "memory")
#define MBARRIER_EXPECT_TX(addr, bytes) \
    asm volatile("mbarrier.arrive.expect_tx.shared.b64 _, [%0], %1;" :: "r"((uint32_t)(addr)), "r"((uint32_t)(bytes)) : "memory")
#define FENCE_PROXY_ASYNC() \
    asm volatile("fence.proxy.async.shared::cta;" ::: "memory")

#define MBARRIER_WAIT_PARITY(mbar_smem_addr, phase_parity) do { \
    uint32_t _mbar = (uint32_t)(mbar_smem_addr); \
    uint32_t _parity = (uint32_t)(phase_parity); \
    uint32_t _done; \
    asm volatile("{\n\t.reg .pred p;\n\t" \
        "mbarrier.try_wait.parity.acquire.cta.shared::cta.b64 p, [%1], %2;\n\t" \
        "selp.b32 %0, 1, 0, p;\n\t}" \
        : "=r"(_done) : "r"(_mbar), "r"(_parity) : "memory"); \
    if (!_done) { \
        asm volatile("{\n\t.reg .pred P1;\n\t" \
            "WAIT_LOOP_%=:\n\t" \
            "mbarrier.try_wait.parity.acquire.cta.shared::cta.b64 P1, [%0], %1, 0x989680;\n\t" \
            "@P1 bra.uni WAIT_DONE_%=;\n\t" \
            "bra.uni WAIT_LOOP_%=;\n\t" \
            "WAIT_DONE_%=:\n\t}" \
            :: "r"(_mbar), "r"(_parity) : "memory"); \
    } \
} while(0)

#define BULK_G2S(dst, src, bytes, mbar) \
    asm volatile("cp.async.bulk.shared::cluster.global.mbarrier::complete_tx::bytes [%0], [%1], %2, [%3];" \
        :: "r"((uint32_t)(dst)), "l"(src), "r"((uint32_t)(bytes)), "r"((uint32_t)(mbar)) : "memory")

__device__ __forceinline__ void ldsm4(uint32_t* r, uint32_t addr) {
    asm volatile("ldmatrix.sync.aligned.m8n8.x4.shared.b16 {%0,%1,%2,%3}, [%4];"
        : "=r"(r[0]), "=r"(r[1]), "=r"(r[2]), "=r"(r[3]) : "r"(addr));
}
__device__ __forceinline__ void mma16816(float* c, const uint32_t* a, const uint32_t* b) {
    asm volatile("mma.sync.aligned.m16n8k16.row.col.f32.bf16.bf16.f32 "
        "{%0,%1,%2,%3}, {%4,%5,%6,%7}, {%8,%9}, {%0,%1,%2,%3};"
        : "+f"(c[0]), "+f"(c[1]), "+f"(c[2]), "+f"(c[3])
        : "r"(a[0]), "r"(a[1]), "r"(a[2]), "r"(a[3]), "r"(b[0]), "r"(b[1]));
}

// =====================================================================
// conversion kernels: fp32 -> (hi, lo) bf16 split, pre-swizzled tiles
// =====================================================================
__device__ __forceinline__ void split4(const float4& v,
                                       unsigned long long& hh, unsigned long long& ll) {
    float f[4] = {v.x, v.y, v.z, v.w};
    unsigned long long h = 0, l = 0;
    #pragma unroll
    for (int i = 0; i < 4; i++) {
        __nv_bfloat16 hb = __float2bfloat16(f[i]);
        float hf = __bfloat162float(hb);
        __nv_bfloat16 lb = __float2bfloat16(f[i] - hf);
        h |= ((unsigned long long)__bfloat16_as_ushort(hb)) << (16 * i);
        l |= ((unsigned long long)__bfloat16_as_ushort(lb)) << (16 * i);
    }
    hh = h; ll = l;
}

__global__ void __launch_bounds__(256) convert_x_kernel(const float* __restrict__ x) {
    int gid = blockIdx.x * 256 + threadIdx.x;
    int m  = gid >> 8;
    int k4 = gid & 255;
    float4 v = *(const float4*)(x + (size_t)m * KK + (k4 << 2));
    unsigned long long hh, ll;
    split4(v, hh, ll);
    int mt = m >> 7, r = m & 127;
    int k = k4 << 2, kc = k >> 6, c = k & 63;
    uint32_t boff = r * 128 + c * 2;
    uint32_t sw = boff ^ ((boff >> 3) & 0x70);
    size_t tb = ((size_t)(mt * 16 + kc)) << 14;
    *(unsigned long long*)(g_xh + tb + sw) = hh;
    *(unsigned long long*)(g_xl + tb + sw) = ll;
}

__global__ void __launch_bounds__(256) convert_w_kernel(
    const float* __restrict__ Wi, const float* __restrict__ Wf,
    const float* __restrict__ Wh) {
    int gid = blockIdx.x * 256 + threadIdx.x;   // 3*1024*256 threads
    int mat = gid >> 18;
    int rem = gid & 262143;
    int d  = rem >> 8;
    int k4 = rem & 255;
    const float* W = (mat == 0) ? Wi : ((mat == 1) ? Wf : Wh);
    float4 v = *(const float4*)(W + (size_t)d * KK + (k4 << 2));
    unsigned long long hh, ll;
    split4(v, hh, ll);
    int nt = d >> 6;
    int r  = ((d >> 3) & 7) * 24 + mat * 8 + (d & 7);   // 8-feature interleave
    int k = k4 << 2, kc = k >> 6, c = k & 63;
    uint32_t boff = r * 128 + c * 2;
    uint32_t sw = boff ^ ((boff >> 3) & 0x70);
    size_t tb = (size_t)(nt * 16 + kc) * 24576;
    *(unsigned long long*)(g_wh + tb + sw) = hh;
    *(unsigned long long*)(g_wl + tb + sw) = ll;
}

// =====================================================================
// HMMA GEMM: CTA 128(M) x 192(N), K chunk 64, 2-stage bulk-copy pipeline.
// Warp grid 2(M) x 4(N): warp tile 64 x 48. 3-product bf16-split into fp32
// register accumulators; fused gate epilogue writes g_logf / g_lv.
// =====================================================================
#define STG_BYTES 81920
#define OFF_AH 0
#define OFF_AL 16384
#define OFF_BH 32768
#define OFF_BL 57344
#define SMEM_TILES 1024

__global__ void __launch_bounds__(256, 1)
gemm_kernel(const float* __restrict__ pbi, const float* __restrict__ pbf,
            const float* __restrict__ pbh) {
    extern __shared__ __align__(1024) unsigned char smem[];
    uint32_t sb = smem_to_u32(smem);
    const int tid = threadIdx.x;
    const int wid = tid >> 5, lane = tid & 31;
    const int warpM = wid & 1;          // 0..1  (64 rows each)
    const int warpN = wid >> 1;         // 0..3  (48 N-rows each)
    const int nt = blockIdx.x;          // 0..15
    const int bt = blockIdx.y;          // 0..255

    if (tid == 0) {
        MBARRIER_INIT(sb + 0, 1);
        MBARRIER_INIT(sb + 8, 1);
        FENCE_PROXY_ASYNC();
    }
    __syncthreads();

    // prologue: issue stage 0 and 1
    if (tid == 0) {
        #pragma unroll
        for (int s = 0; s < 2; s++) {
            uint32_t fb = sb + s * 8;
            uint32_t dst = sb + SMEM_TILES + s * STG_BYTES;
            const unsigned char* ah = g_xh + (((size_t)(bt * 16 + s)) << 14);
            const unsigned char* al = g_xl + (((size_t)(bt * 16 + s)) << 14);
            const unsigned char* bh_ = g_wh + (size_t)(nt * 16 + s) * 24576;
            const unsigned char* bl_ = g_wl + (size_t)(nt * 16 + s) * 24576;
            MBARRIER_EXPECT_TX(fb, STG_BYTES);
            BULK_G2S(dst + OFF_AH, ah, 16384, fb);
            BULK_G2S(dst + OFF_AL, al, 16384, fb);
            BULK_G2S(dst + OFF_BH, bh_, 24576, fb);
            BULK_G2S(dst + OFF_BL, bl_, 24576, fb);
        }
    }

    // fragment address components (per thread, constant over k)
    const int g = lane >> 3;            // 0..3 ldmatrix lane-group
    const uint32_t xorv = (uint32_t)((lane & 7) << 4);
    uint32_t aoff[4], boff[3];
    #pragma unroll
    for (int mt = 0; mt < 4; mt++) {
        int row = warpM * 64 + mt * 16 + (g & 1) * 8 + (lane & 7);
        aoff[mt] = (uint32_t)(row * 128);
    }
    const uint32_t acol16 = (uint32_t)((g >> 1) * 16);   // byte offset from k-group
    #pragma unroll
    for (int p = 0; p < 3; p++) {
        int row = warpN * 48 + p * 16 + (g >> 1) * 8 + (lane & 7);
        boff[p] = (uint32_t)(row * 128);
    }
    const uint32_t bcol16 = (uint32_t)((g & 1) * 16);

    float acc[4][6][4];
    #pragma unroll
    for (int mt = 0; mt < 4; mt++)
        #pragma unroll
        for (int n8 = 0; n8 < 6; n8++)
            #pragma unroll
            for (int e = 0; e < 4; e++)
                acc[mt][n8][e] = 0.0f;

    #pragma unroll 1
    for (int c = 0; c < 16; c++) {
        const int s = c & 1;
        const uint32_t ph = (uint32_t)((c >> 1) & 1);
        MBARRIER_WAIT_PARITY(sb + s * 8, ph);
        const uint32_t st = sb + SMEM_TILES + s * STG_BYTES;

        #pragma unroll 1
        for (int ks = 0; ks < 4; ks++) {
            const uint32_t ca = (uint32_t)(ks * 32);
            const uint32_t cswA = (ca + acol16) ^ xorv;
            const uint32_t cswB = (ca + bcol16) ^ xorv;
            uint32_t Ah[4][4], Al[4][4], Bh[3][4], Bl[3][4];
            #pragma unroll
            for (int mt = 0; mt < 4; mt++) {
                ldsm4(Ah[mt], st + OFF_AH + aoff[mt] + cswA);
                ldsm4(Al[mt], st + OFF_AL + aoff[mt] + cswA);
            }
            #pragma unroll
            for (int p = 0; p < 3; p++) {
                ldsm4(Bh[p], st + OFF_BH + boff[p] + cswB);
                ldsm4(Bl[p], st + OFF_BL + boff[p] + cswB);
            }
            // product Ah*Bh
            #pragma unroll
            for (int mt = 0; mt < 4; mt++)
                #pragma unroll
                for (int n8 = 0; n8 < 6; n8++)
                    mma16816(acc[mt][n8], Ah[mt], &Bh[n8 >> 1][(n8 & 1) * 2]);
            // product Al*Bh
            #pragma unroll
            for (int mt = 0; mt < 4; mt++)
                #pragma unroll
                for (int n8 = 0; n8 < 6; n8++)
                    mma16816(acc[mt][n8], Al[mt], &Bh[n8 >> 1][(n8 & 1) * 2]);
            // product Ah*Bl
            #pragma unroll
            for (int mt = 0; mt < 4; mt++)
                #pragma unroll
                for (int n8 = 0; n8 < 6; n8++)
                    mma16816(acc[mt][n8], Ah[mt], &Bl[n8 >> 1][(n8 & 1) * 2]);
        }

        __syncthreads();
        if (tid == 0 && c + 2 < 16) {
            const int cn = c + 2;
            uint32_t fb = sb + s * 8;
            uint32_t dst = sb + SMEM_TILES + s * STG_BYTES;
            const unsigned char* ah = g_xh + (((size_t)(bt * 16 + cn)) << 14);
            const unsigned char* al = g_xl + (((size_t)(bt * 16 + cn)) << 14);
            const unsigned char* bh_ = g_wh + (size_t)(nt * 16 + cn) * 24576;
            const unsigned char* bl_ = g_wl + (size_t)(nt * 16 + cn) * 24576;
            MBARRIER_EXPECT_TX(fb, STG_BYTES);
            BULK_G2S(dst + OFF_AH, ah, 16384, fb);
            BULK_G2S(dst + OFF_AL, al, 16384, fb);
            BULK_G2S(dst + OFF_BH, bh_, 24576, fb);
            BULK_G2S(dst + OFF_BL, bl_, 24576, fb);
        }
    }

    // ---------------- fused gate epilogue ----------------
    // acc[mt][3g+mat] holds z_mat for features d0..d0+7 of group g.
    #pragma unroll
    for (int gg = 0; gg < 2; gg++) {
        const int d0 = nt * 64 + (warpN * 2 + gg) * 8 + (lane & 3) * 2;
        const float bi0 = pbi[d0], bi1 = pbi[d0 + 1];
        const float bf0 = pbf[d0], bf1 = pbf[d0 + 1];
        const float bh0 = pbh[d0], bh1 = pbh[d0 + 1];
        #pragma unroll
        for (int mt = 0; mt < 4; mt++) {
            const int mrow0 = bt * 128 + warpM * 64 + mt * 16 + (lane >> 2);
            const float* zi = acc[mt][3 * gg + 0];
            const float* zf = acc[mt][3 * gg + 1];
            const float* zh = acc[mt][3 * gg + 2];
            #pragma unroll
            for (int e = 0; e < 2; e++) {
                const int m = mrow0 + e * 8;
                const int b = m >> 12;
                float z_i0 = zi[2 * e] + bi0, z_i1 = zi[2 * e + 1] + bi1;
                float z_f0 = zf[2 * e] + bf0, z_f1 = zf[2 * e + 1] + bf1;
                float z_h0 = zh[2 * e] + bh0, z_h1 = zh[2 * e + 1] + bh1;
                float df0 = sp(-z_f0) - sp(-z_i0);
                float df1 = sp(-z_f1) - sp(-z_i1);
                float lf0 = -sp(df0), lf1 = -sp(df1);
                float lv0 = -sp(-df0) + log_g(z_h0);
                float lv1 = -sp(-df1) + log_g(z_h1);
                *(float2*)(g_logf + (size_t)m * DD + d0) = make_float2(lf0, lf1);
                *(float2*)(g_lv + (size_t)(m + b + 1) * DD + d0) = make_float2(lv0, lv1);
            }
        }
    }

    __syncthreads();
    if (tid == 0) {
        MBARRIER_INVAL(sb + 0);
        MBARRIER_INVAL(sb + 8);
    }
}

// =====================================================================
// log_values[:,0,:] = log_g(h_0)
// =====================================================================
__global__ void h0_kernel(const float* __restrict__ h0) {
    int i = blockIdx.x * 256 + threadIdx.x;
    int b = i >> 10;
    int d = i & (DD - 1);
    g_lv[(size_t)b * TP1 * DD + d] = log_g(h0[i]);
}

// =====================================================================
// a_star: feature-dim cumsum of log_f, shifted one row in time
// =====================================================================
__global__ void __launch_bounds__(256) cumsum_kernel() {
    int r = blockIdx.x;              // 0 .. B*TP1-1
    int b = r / TP1;
    int t = r - b * TP1;
    int tid = threadIdx.x;
    float4* dst = (float4*)(g_as + (size_t)r * DD);

    if (t == 0) {
        dst[tid] = make_float4(0.f, 0.f, 0.f, 0.f);
        return;
    }
    const float4* src = (const float4*)(g_logf + (size_t)(b * TT + t - 1) * DD);
    float4 v = src[tid];
    v.y += v.x; v.z += v.y; v.w += v.z;
    float tsum = v.w;

    int lane = tid & 31, warp = tid >> 5;
    #pragma unroll
    for (int off = 1; off < 32; off <<= 1) {
        float n = __shfl_up_sync(0xffffffffu, tsum, off);
        if (lane >= off) tsum += n;
    }
    __shared__ float wsum[8];
    if (lane == 31) wsum[warp] = tsum;
    __syncthreads();
    float prev = tsum - v.w;
    for (int w = 0; w < warp; w++) prev += wsum[w];
    v.x += prev; v.y += prev; v.z += prev; v.w += prev;
    dst[tid] = v;
}

// =====================================================================
// streaming logcumsumexp over time; out = exp(a_star + log_h)
// =====================================================================
__global__ void __launch_bounds__(256) scan_kernel(float* __restrict__ out) {
    int g = blockIdx.x * 256 + threadIdx.x;   // < B*D
    int b = g >> 10;
    int d = g & (DD - 1);
    size_t base = (size_t)b * TP1 * DD + d;

    float m = -INFINITY;
    float s = 0.0f;
    for (int t = 0; t < TP1; t++) {
        size_t idx = base + (size_t)t * DD;
        float a  = g_as[idx];
        float v  = g_lv[idx] - a;
        float mn = fmaxf(m, v);
        s = s * expf(m - mn) + expf(v - mn);
        m = mn;
        out[idx] = expf(a + m + logf(s));
    }
}

// =====================================================================
extern "C" void kernel_launch(void* const* d_in, const int* in_sizes, int n_in,
                              void* d_out, int out_size)
{
    const float* x  = (const float*)d_in[0];
    const float* h0 = (const float*)d_in[1];
    const float* Wi = (const float*)d_in[2];
    const float* bi = (const float*)d_in[3];
    const float* Wf = (const float*)d_in[4];
    const float* bf = (const float*)d_in[5];
    const float* Wh = (const float*)d_in[6];
    const float* bh = (const float*)d_in[7];
    float* out = (float*)d_out;
    (void)in_sizes; (void)n_in; (void)out_size;

    const int smem_bytes = SMEM_TILES + 2 * STG_BYTES;   // 164864
    cudaFuncSetAttribute(gemm_kernel, cudaFuncAttributeMaxDynamicSharedMemorySize, smem_bytes);

    convert_x_kernel<<<MM, 256>>>(x);
    convert_w_kernel<<<3072, 256>>>(Wi, Wf, Wh);
    h0_kernel<<<(BB * DD) / 256, 256>>>(h0);
    gemm_kernel<<<dim3(16, 256), 256, smem_bytes>>>(bi, bf, bh);
    cumsum_kernel<<<BB * TP1, 256>>>();
    scan_kernel<<<(BB * DD) / 256, 256>>>(out);
}

// round 6
// speedup vs baseline: 3.6057x; 1.7236x over previous
#include <cuda_runtime.h>
#include <cuda_bf16.h>
#include <math.h>
#include <stdint.h>

#define BB 8
#define TT 4096
#define TP1 4097
#define DD 1024
#define KK 1024
#define MM (BB*TT)
#define NP 3072
#define BD (BB*DD)      // 8192
#define CS 128          // scan chunk size
#define CH 33           // ceil(4097/128)

// ---------------- scratch (device globals) ----------------
__device__ __align__(16) unsigned char g_xh[(size_t)MM * KK * 2];
__device__ __align__(16) unsigned char g_xl[(size_t)MM * KK * 2];
__device__ __align__(16) unsigned char g_wh[(size_t)NP * KK * 2];
__device__ __align__(16) unsigned char g_wl[(size_t)NP * KK * 2];

__device__ float g_logf[(size_t)MM * DD];        // log_f [B,T,D]
__device__ float g_lv  [(size_t)BB * TP1 * DD];  // log_values [B,T+1,D]
__device__ float g_as  [(size_t)BB * TP1 * DD];  // a_star [B,T+1,D]

// chunked-scan state: [chunk][bd] layout for coalescing
__device__ float g_cm[CH * BD];
__device__ float g_cs[CH * BD];
__device__ float g_pm[CH * BD];
__device__ float g_ps[CH * BD];

// ---------------- math helpers ----------------
__device__ __forceinline__ float sp(float x) {          // stable softplus
    return fmaxf(x, 0.0f) + log1pf(expf(-fabsf(x)));
}
__device__ __forceinline__ float log_g(float x) {
    return (x >= 0.0f) ? logf(x + 0.5f) : -sp(-x);
}

// ---------------- PTX helpers ----------------
__device__ __forceinline__ uint32_t smem_to_u32(const void* p) {
    uint32_t a;
    asm("{ .reg .u64 t; cvta.to.shared.u64 t, %1; cvt.u32.u64 %0, t; }"
        : "=r"(a) : "l"(p));
    return a;
}

#define MBARRIER_INIT(addr, cnt) \
    asm volatile("mbarrier.init.shared.b64 [%0], %1;" :: "r"((uint32_t)(addr)), "r"((uint32_t)(cnt)) : "memory")
#define MBARRIER_INVAL(addr) \
    asm volatile("mbarrier.inval.shared.b64 [%0];" :: "r"((uint32_t)(addr)) : "memory")
#define MBARRIER_EXPECT_TX(addr, bytes) \
    asm volatile("mbarrier.arrive.expect_tx.shared.b64 _, [%0], %1;" :: "r"((uint32_t)(addr)), "r"((uint32_t)(bytes)) : "memory")
#define FENCE_PROXY_ASYNC() \
    asm volatile("fence.proxy.async.shared::cta;" ::: "memory")

#define MBARRIER_WAIT_PARITY(mbar_smem_addr, phase_parity) do { \
    uint32_t _mbar = (uint32_t)(mbar_smem_addr); \
    uint32_t _parity = (uint32_t)(phase_parity); \
    uint32_t _done; \
    asm volatile("{\n\t.reg .pred p;\n\t" \
        "mbarrier.try_wait.parity.acquire.cta.shared::cta.b64 p, [%1], %2;\n\t" \
        "selp.b32 %0, 1, 0, p;\n\t}" \
        : "=r"(_done) : "r"(_mbar), "r"(_parity) : "memory"); \
    if (!_done) { \
        asm volatile("{\n\t.reg .pred P1;\n\t" \
            "WAIT_LOOP_%=:\n\t" \
            "mbarrier.try_wait.parity.acquire.cta.shared::cta.b64 P1, [%0], %1, 0x989680;\n\t" \
            "@P1 bra.uni WAIT_DONE_%=;\n\t" \
            "bra.uni WAIT_LOOP_%=;\n\t" \
            "WAIT_DONE_%=:\n\t}" \
            :: "r"(_mbar), "r"(_parity) : "memory"); \
    } \
} while(0)

#define BULK_G2S(dst, src, bytes, mbar) \
    asm volatile("cp.async.bulk.shared::cluster.global.mbarrier::complete_tx::bytes [%0], [%1], %2, [%3];" \
        :: "r"((uint32_t)(dst)), "l"(src), "r"((uint32_t)(bytes)), "r"((uint32_t)(mbar)) : "memory")

__device__ __forceinline__ void ldsm4(uint32_t* r, uint32_t addr) {
    asm volatile("ldmatrix.sync.aligned.m8n8.x4.shared.b16 {%0,%1,%2,%3}, [%4];"
        : "=r"(r[0]), "=r"(r[1]), "=r"(r[2]), "=r"(r[3]) : "r"(addr));
}
__device__ __forceinline__ void mma16816(float* c, const uint32_t* a, const uint32_t* b) {
    asm volatile("mma.sync.aligned.m16n8k16.row.col.f32.bf16.bf16.f32 "
        "{%0,%1,%2,%3}, {%4,%5,%6,%7}, {%8,%9}, {%0,%1,%2,%3};"
        : "+f"(c[0]), "+f"(c[1]), "+f"(c[2]), "+f"(c[3])
        : "r"(a[0]), "r"(a[1]), "r"(a[2]), "r"(a[3]), "r"(b[0]), "r"(b[1]));
}

// =====================================================================
// conversion kernels: fp32 -> (hi, lo) bf16 split, pre-swizzled tiles
// =====================================================================
__device__ __forceinline__ void split4(const float4& v,
                                       unsigned long long& hh, unsigned long long& ll) {
    float f[4] = {v.x, v.y, v.z, v.w};
    unsigned long long h = 0, l = 0;
    #pragma unroll
    for (int i = 0; i < 4; i++) {
        __nv_bfloat16 hb = __float2bfloat16(f[i]);
        float hf = __bfloat162float(hb);
        __nv_bfloat16 lb = __float2bfloat16(f[i] - hf);
        h |= ((unsigned long long)__bfloat16_as_ushort(hb)) << (16 * i);
        l |= ((unsigned long long)__bfloat16_as_ushort(lb)) << (16 * i);
    }
    hh = h; ll = l;
}

__global__ void __launch_bounds__(256) convert_x_kernel(const float* __restrict__ x) {
    int gid = blockIdx.x * 256 + threadIdx.x;
    int m  = gid >> 8;
    int k4 = gid & 255;
    float4 v = *(const float4*)(x + (size_t)m * KK + (k4 << 2));
    unsigned long long hh, ll;
    split4(v, hh, ll);
    int mt = m >> 7, r = m & 127;
    int k = k4 << 2, kc = k >> 6, c = k & 63;
    uint32_t boff = r * 128 + c * 2;
    uint32_t sw = boff ^ ((boff >> 3) & 0x70);
    size_t tb = ((size_t)(mt * 16 + kc)) << 14;
    *(unsigned long long*)(g_xh + tb + sw) = hh;
    *(unsigned long long*)(g_xl + tb + sw) = ll;
}

__global__ void __launch_bounds__(256) convert_w_kernel(
    const float* __restrict__ Wi, const float* __restrict__ Wf,
    const float* __restrict__ Wh) {
    int gid = blockIdx.x * 256 + threadIdx.x;   // 3*1024*256 threads
    int mat = gid >> 18;
    int rem = gid & 262143;
    int d  = rem >> 8;
    int k4 = rem & 255;
    const float* W = (mat == 0) ? Wi : ((mat == 1) ? Wf : Wh);
    float4 v = *(const float4*)(W + (size_t)d * KK + (k4 << 2));
    unsigned long long hh, ll;
    split4(v, hh, ll);
    int nt = d >> 6;
    int r  = ((d >> 3) & 7) * 24 + mat * 8 + (d & 7);   // 8-feature interleave
    int k = k4 << 2, kc = k >> 6, c = k & 63;
    uint32_t boff = r * 128 + c * 2;
    uint32_t sw = boff ^ ((boff >> 3) & 0x70);
    size_t tb = (size_t)(nt * 16 + kc) * 24576;
    *(unsigned long long*)(g_wh + tb + sw) = hh;
    *(unsigned long long*)(g_wl + tb + sw) = ll;
}

// =====================================================================
// HMMA GEMM: CTA 128(M) x 192(N), K chunk 64, 2-stage bulk-copy pipeline.
// Warp grid 2(M) x 4(N): warp tile 64 x 48. 3-product bf16-split into fp32
// register accumulators; fused gate epilogue writes g_logf / g_lv.
// ks loop FULLY UNROLLED so ptxas pipelines ldmatrix under HMMA.
// =====================================================================
#define STG_BYTES 81920
#define OFF_AH 0
#define OFF_AL 16384
#define OFF_BH 32768
#define OFF_BL 57344
#define SMEM_TILES 1024

__global__ void __launch_bounds__(256, 1)
gemm_kernel(const float* __restrict__ pbi, const float* __restrict__ pbf,
            const float* __restrict__ pbh) {
    extern __shared__ __align__(1024) unsigned char smem[];
    uint32_t sb = smem_to_u32(smem);
    const int tid = threadIdx.x;
    const int wid = tid >> 5, lane = tid & 31;
    const int warpM = wid & 1;          // 0..1  (64 rows each)
    const int warpN = wid >> 1;         // 0..3  (48 N-rows each)
    const int nt = blockIdx.x;          // 0..15
    const int bt = blockIdx.y;          // 0..255

    if (tid == 0) {
        MBARRIER_INIT(sb + 0, 1);
        MBARRIER_INIT(sb + 8, 1);
        FENCE_PROXY_ASYNC();
    }
    __syncthreads();

    // prologue: issue stage 0 and 1
    if (tid == 0) {
        #pragma unroll
        for (int s = 0; s < 2; s++) {
            uint32_t fb = sb + s * 8;
            uint32_t dst = sb + SMEM_TILES + s * STG_BYTES;
            const unsigned char* ah = g_xh + (((size_t)(bt * 16 + s)) << 14);
            const unsigned char* al = g_xl + (((size_t)(bt * 16 + s)) << 14);
            const unsigned char* bh_ = g_wh + (size_t)(nt * 16 + s) * 24576;
            const unsigned char* bl_ = g_wl + (size_t)(nt * 16 + s) * 24576;
            MBARRIER_EXPECT_TX(fb, STG_BYTES);
            BULK_G2S(dst + OFF_AH, ah, 16384, fb);
            BULK_G2S(dst + OFF_AL, al, 16384, fb);
            BULK_G2S(dst + OFF_BH, bh_, 24576, fb);
            BULK_G2S(dst + OFF_BL, bl_, 24576, fb);
        }
    }

    // fragment address components (per thread, constant over k)
    const int g = lane >> 3;            // 0..3 ldmatrix lane-group
    const uint32_t xorv = (uint32_t)((lane & 7) << 4);
    uint32_t aoff[4], boff[3];
    #pragma unroll
    for (int mt = 0; mt < 4; mt++) {
        int row = warpM * 64 + mt * 16 + (g & 1) * 8 + (lane & 7);
        aoff[mt] = (uint32_t)(row * 128);
    }
    const uint32_t acol16 = (uint32_t)((g >> 1) * 16);
    #pragma unroll
    for (int p = 0; p < 3; p++) {
        int row = warpN * 48 + p * 16 + (g >> 1) * 8 + (lane & 7);
        boff[p] = (uint32_t)(row * 128);
    }
    const uint32_t bcol16 = (uint32_t)((g & 1) * 16);

    float acc[4][6][4];
    #pragma unroll
    for (int mt = 0; mt < 4; mt++)
        #pragma unroll
        for (int n8 = 0; n8 < 6; n8++)
            #pragma unroll
            for (int e = 0; e < 4; e++)
                acc[mt][n8][e] = 0.0f;

    #pragma unroll 1
    for (int c = 0; c < 16; c++) {
        const int s = c & 1;
        const uint32_t ph = (uint32_t)((c >> 1) & 1);
        MBARRIER_WAIT_PARITY(sb + s * 8, ph);
        const uint32_t st = sb + SMEM_TILES + s * STG_BYTES;

        #pragma unroll
        for (int ks = 0; ks < 4; ks++) {
            const uint32_t ca = (uint32_t)(ks * 32);
            const uint32_t cswA = (ca + acol16) ^ xorv;
            const uint32_t cswB = (ca + bcol16) ^ xorv;
            uint32_t Ah[4][4], Al[4][4], Bh[3][4], Bl[3][4];
            #pragma unroll
            for (int mt = 0; mt < 4; mt++) {
                ldsm4(Ah[mt], st + OFF_AH + aoff[mt] + cswA);
                ldsm4(Al[mt], st + OFF_AL + aoff[mt] + cswA);
            }
            #pragma unroll
            for (int p = 0; p < 3; p++) {
                ldsm4(Bh[p], st + OFF_BH + boff[p] + cswB);
                ldsm4(Bl[p], st + OFF_BL + boff[p] + cswB);
            }
            #pragma unroll
            for (int mt = 0; mt < 4; mt++)
                #pragma unroll
                for (int n8 = 0; n8 < 6; n8++)
                    mma16816(acc[mt][n8], Ah[mt], &Bh[n8 >> 1][(n8 & 1) * 2]);
            #pragma unroll
            for (int mt = 0; mt < 4; mt++)
                #pragma unroll
                for (int n8 = 0; n8 < 6; n8++)
                    mma16816(acc[mt][n8], Al[mt], &Bh[n8 >> 1][(n8 & 1) * 2]);
            #pragma unroll
            for (int mt = 0; mt < 4; mt++)
                #pragma unroll
                for (int n8 = 0; n8 < 6; n8++)
                    mma16816(acc[mt][n8], Ah[mt], &Bl[n8 >> 1][(n8 & 1) * 2]);
        }

        __syncthreads();
        if (tid == 0 && c + 2 < 16) {
            const int cn = c + 2;
            uint32_t fb = sb + s * 8;
            uint32_t dst = sb + SMEM_TILES + s * STG_BYTES;
            const unsigned char* ah = g_xh + (((size_t)(bt * 16 + cn)) << 14);
            const unsigned char* al = g_xl + (((size_t)(bt * 16 + cn)) << 14);
            const unsigned char* bh_ = g_wh + (size_t)(nt * 16 + cn) * 24576;
            const unsigned char* bl_ = g_wl + (size_t)(nt * 16 + cn) * 24576;
            MBARRIER_EXPECT_TX(fb, STG_BYTES);
            BULK_G2S(dst + OFF_AH, ah, 16384, fb);
            BULK_G2S(dst + OFF_AL, al, 16384, fb);
            BULK_G2S(dst + OFF_BH, bh_, 24576, fb);
            BULK_G2S(dst + OFF_BL, bl_, 24576, fb);
        }
    }

    // ---------------- fused gate epilogue ----------------
    #pragma unroll
    for (int gg = 0; gg < 2; gg++) {
        const int d0 = nt * 64 + (warpN * 2 + gg) * 8 + (lane & 3) * 2;
        const float bi0 = pbi[d0], bi1 = pbi[d0 + 1];
        const float bf0 = pbf[d0], bf1 = pbf[d0 + 1];
        const float bh0 = pbh[d0], bh1 = pbh[d0 + 1];
        #pragma unroll
        for (int mt = 0; mt < 4; mt++) {
            const int mrow0 = bt * 128 + warpM * 64 + mt * 16 + (lane >> 2);
            const float* zi = acc[mt][3 * gg + 0];
            const float* zf = acc[mt][3 * gg + 1];
            const float* zh = acc[mt][3 * gg + 2];
            #pragma unroll
            for (int e = 0; e < 2; e++) {
                const int m = mrow0 + e * 8;
                const int b = m >> 12;
                float z_i0 = zi[2 * e] + bi0, z_i1 = zi[2 * e + 1] + bi1;
                float z_f0 = zf[2 * e] + bf0, z_f1 = zf[2 * e + 1] + bf1;
                float z_h0 = zh[2 * e] + bh0, z_h1 = zh[2 * e + 1] + bh1;
                float df0 = sp(-z_f0) - sp(-z_i0);
                float df1 = sp(-z_f1) - sp(-z_i1);
                float lf0 = -sp(df0), lf1 = -sp(df1);
                float lv0 = -sp(-df0) + log_g(z_h0);
                float lv1 = -sp(-df1) + log_g(z_h1);
                *(float2*)(g_logf + (size_t)m * DD + d0) = make_float2(lf0, lf1);
                *(float2*)(g_lv + (size_t)(m + b + 1) * DD + d0) = make_float2(lv0, lv1);
            }
        }
    }

    __syncthreads();
    if (tid == 0) {
        MBARRIER_INVAL(sb + 0);
        MBARRIER_INVAL(sb + 8);
    }
}

// =====================================================================
// log_values[:,0,:] = log_g(h_0)
// =====================================================================
__global__ void h0_kernel(const float* __restrict__ h0) {
    int i = blockIdx.x * 256 + threadIdx.x;
    int b = i >> 10;
    int d = i & (DD - 1);
    g_lv[(size_t)b * TP1 * DD + d] = log_g(h0[i]);
}

// =====================================================================
// a_star: feature-dim cumsum of log_f, shifted one row in time
// =====================================================================
__global__ void __launch_bounds__(256) cumsum_kernel() {
    int r = blockIdx.x;              // 0 .. B*TP1-1
    int b = r / TP1;
    int t = r - b * TP1;
    int tid = threadIdx.x;
    float4* dst = (float4*)(g_as + (size_t)r * DD);

    if (t == 0) {
        dst[tid] = make_float4(0.f, 0.f, 0.f, 0.f);
        return;
    }
    const float4* src = (const float4*)(g_logf + (size_t)(b * TT + t - 1) * DD);
    float4 v = src[tid];
    v.y += v.x; v.z += v.y; v.w += v.z;
    float tsum = v.w;

    int lane = tid & 31, warp = tid >> 5;
    #pragma unroll
    for (int off = 1; off < 32; off <<= 1) {
        float n = __shfl_up_sync(0xffffffffu, tsum, off);
        if (lane >= off) tsum += n;
    }
    __shared__ float wsum[8];
    if (lane == 31) wsum[warp] = tsum;
    __syncthreads();
    float prev = tsum - v.w;
    for (int w = 0; w < warp; w++) prev += wsum[w];
    v.x += prev; v.y += prev; v.z += prev; v.w += prev;
    dst[tid] = v;
}

// =====================================================================
// chunked logcumsumexp over time (3 passes, fully parallel)
// =====================================================================
__global__ void __launch_bounds__(256) scan_a_kernel() {
    int gid = blockIdx.x * 256 + threadIdx.x;   // < CH*BD
    int c  = gid >> 13;                          // /8192
    int bd = gid & (BD - 1);
    int b = bd >> 10, d = bd & (DD - 1);
    int t0 = c * CS;
    int t1 = t0 + CS; if (t1 > TP1) t1 = TP1;
    size_t base = (size_t)b * TP1 * DD + d;

    float m = -INFINITY, s = 0.0f;
    for (int t = t0; t < t1; t++) {
        size_t idx = base + (size_t)t * DD;
        float v  = g_lv[idx] - g_as[idx];
        float mn = fmaxf(m, v);
        s = s * expf(m - mn) + expf(v - mn);
        m = mn;
    }
    g_cm[gid] = m;
    g_cs[gid] = s;
}

__global__ void __launch_bounds__(256) scan_b_kernel() {
    int bd = blockIdx.x * 256 + threadIdx.x;    // < BD
    float M = -INFINITY, S = 0.0f;
    #pragma unroll 1
    for (int c = 0; c < CH; c++) {
        int i = c * BD + bd;
        g_pm[i] = M;
        g_ps[i] = S;
        float m = g_cm[i], s = g_cs[i];
        float mn = fmaxf(M, m);
        S = S * expf(M - mn) + s * expf(m - mn);
        M = mn;
    }
}

__global__ void __launch_bounds__(256) scan_c_kernel(float* __restrict__ out) {
    int gid = blockIdx.x * 256 + threadIdx.x;   // < CH*BD
    int c  = gid >> 13;
    int bd = gid & (BD - 1);
    int b = bd >> 10, d = bd & (DD - 1);
    int t0 = c * CS;
    int t1 = t0 + CS; if (t1 > TP1) t1 = TP1;
    size_t base = (size_t)b * TP1 * DD + d;

    float m = g_pm[gid];
    float s = g_ps[gid];
    for (int t = t0; t < t1; t++) {
        size_t idx = base + (size_t)t * DD;
        float a  = g_as[idx];
        float v  = g_lv[idx] - a;
        float mn = fmaxf(m, v);
        s = s * expf(m - mn) + expf(v - mn);
        m = mn;
        out[idx] = expf(a + m + logf(s));
    }
}

// =====================================================================
extern "C" void kernel_launch(void* const* d_in, const int* in_sizes, int n_in,
                              void* d_out, int out_size)
{
    const float* x  = (const float*)d_in[0];
    const float* h0 = (const float*)d_in[1];
    const float* Wi = (const float*)d_in[2];
    const float* bi = (const float*)d_in[3];
    const float* Wf = (const float*)d_in[4];
    const float* bf = (const float*)d_in[5];
    const float* Wh = (const float*)d_in[6];
    const float* bh = (const float*)d_in[7];
    float* out = (float*)d_out;
    (void)in_sizes; (void)n_in; (void)out_size;

    const int smem_bytes = SMEM_TILES + 2 * STG_BYTES;   // 164864
    cudaFuncSetAttribute(gemm_kernel, cudaFuncAttributeMaxDynamicSharedMemorySize, smem_bytes);

    convert_x_kernel<<<MM, 256>>>(x);
    convert_w_kernel<<<3072, 256>>>(Wi, Wf, Wh);
    h0_kernel<<<(BB * DD) / 256, 256>>>(h0);
    gemm_kernel<<<dim3(16, 256), 256, smem_bytes>>>(bi, bf, bh);
    cumsum_kernel<<<BB * TP1, 256>>>();
    scan_a_kernel<<<(CH * BD) / 256, 256>>>();
    scan_b_kernel<<<BD / 256, 256>>>();
    scan_c_kernel<<<(CH * BD) / 256, 256>>>(out);
}

// round 7
// speedup vs baseline: 3.6696x; 1.0177x over previous
#include <cuda_runtime.h>
#include <cuda_bf16.h>
#include <math.h>
#include <stdint.h>

#define BB 8
#define TT 4096
#define TP1 4097
#define DD 1024
#define KK 1024
#define MM (BB*TT)
#define NP 3072
#define BD (BB*DD)      // 8192
#define CS 128          // scan chunk size
#define CH 33           // ceil(4097/128)

// ---------------- scratch (device globals) ----------------
__device__ __align__(16) unsigned char g_xh[(size_t)MM * KK * 2];
__device__ __align__(16) unsigned char g_xl[(size_t)MM * KK * 2];
__device__ __align__(16) unsigned char g_wh[(size_t)NP * KK * 2];
__device__ __align__(16) unsigned char g_wl[(size_t)NP * KK * 2];

__device__ float g_logf[(size_t)MM * DD];        // log_f [B,T,D]
__device__ float g_lv  [(size_t)BB * TP1 * DD];  // log_values [B,T+1,D]
__device__ float g_as  [(size_t)BB * TP1 * DD];  // a_star [B,T+1,D]

// chunked-scan state: [chunk][bd] layout for coalescing
__device__ float g_cm[CH * BD];
__device__ float g_cs[CH * BD];
__device__ float g_pm[CH * BD];
__device__ float g_ps[CH * BD];

// ---------------- math helpers ----------------
__device__ __forceinline__ float sp(float x) {          // stable softplus
    return fmaxf(x, 0.0f) + log1pf(expf(-fabsf(x)));
}
__device__ __forceinline__ float log_g(float x) {
    return (x >= 0.0f) ? logf(x + 0.5f) : -sp(-x);
}

// ---------------- PTX helpers ----------------
__device__ __forceinline__ uint32_t smem_to_u32(const void* p) {
    uint32_t a;
    asm("{ .reg .u64 t; cvta.to.shared.u64 t, %1; cvt.u32.u64 %0, t; }"
        : "=r"(a) : "l"(p));
    return a;
}

#define MBARRIER_INIT(addr, cnt) \
    asm volatile("mbarrier.init.shared.b64 [%0], %1;" :: "r"((uint32_t)(addr)), "r"((uint32_t)(cnt)) : "memory")
#define MBARRIER_INVAL(addr) \
    asm volatile("mbarrier.inval.shared.b64 [%0];" :: "r"((uint32_t)(addr)) : "memory")
#define MBARRIER_EXPECT_TX(addr, bytes) \
    asm volatile("mbarrier.arrive.expect_tx.shared.b64 _, [%0], %1;" :: "r"((uint32_t)(addr)), "r"((uint32_t)(bytes)) : "memory")
#define MBARRIER_ARRIVE(addr) \
    asm volatile("mbarrier.arrive.shared.b64 _, [%0];" :: "r"((uint32_t)(addr)) : "memory")
#define FENCE_PROXY_ASYNC() \
    asm volatile("fence.proxy.async.shared::cta;" ::: "memory")

#define MBARRIER_WAIT_PARITY(mbar_smem_addr, phase_parity) do { \
    uint32_t _mbar = (uint32_t)(mbar_smem_addr); \
    uint32_t _parity = (uint32_t)(phase_parity); \
    uint32_t _done; \
    asm volatile("{\n\t.reg .pred p;\n\t" \
        "mbarrier.try_wait.parity.acquire.cta.shared::cta.b64 p, [%1], %2;\n\t" \
        "selp.b32 %0, 1, 0, p;\n\t}" \
        : "=r"(_done) : "r"(_mbar), "r"(_parity) : "memory"); \
    if (!_done) { \
        asm volatile("{\n\t.reg .pred P1;\n\t" \
            "WAIT_LOOP_%=:\n\t" \
            "mbarrier.try_wait.parity.acquire.cta.shared::cta.b64 P1, [%0], %1, 0x989680;\n\t" \
            "@P1 bra.uni WAIT_DONE_%=;\n\t" \
            "bra.uni WAIT_LOOP_%=;\n\t" \
            "WAIT_DONE_%=:\n\t}" \
            :: "r"(_mbar), "r"(_parity) : "memory"); \
    } \
} while(0)

#define MBARRIER_WAIT_PARITY_RELAXED(mbar_smem_addr, phase_parity) do { \
    uint32_t _mbar = (uint32_t)(mbar_smem_addr); \
    uint32_t _parity = (uint32_t)(phase_parity); \
    uint32_t _done; \
    asm volatile("{\n\t.reg .pred p;\n\t" \
        "mbarrier.try_wait.parity.relaxed.cta.shared::cta.b64 p, [%1], %2, 0x989680;\n\t" \
        "selp.b32 %0, 1, 0, p;\n\t}" \
        : "=r"(_done) : "r"(_mbar), "r"(_parity) : "memory"); \
    if (!_done) { \
        asm volatile("{\n\t.reg .pred P1;\n\t" \
            "WAIT_LOOP_%=:\n\t" \
            "mbarrier.try_wait.parity.relaxed.cta.shared::cta.b64 P1, [%0], %1, 0x989680;\n\t" \
            "@P1 bra.uni WAIT_DONE_%=;\n\t" \
            "bra.uni WAIT_LOOP_%=;\n\t" \
            "WAIT_DONE_%=:\n\t}" \
            :: "r"(_mbar), "r"(_parity) : "memory"); \
    } \
} while(0)

#define BULK_G2S(dst, src, bytes, mbar) \
    asm volatile("cp.async.bulk.shared::cluster.global.mbarrier::complete_tx::bytes [%0], [%1], %2, [%3];" \
        :: "r"((uint32_t)(dst)), "l"(src), "r"((uint32_t)(bytes)), "r"((uint32_t)(mbar)) : "memory")

__device__ __forceinline__ void ldsm4(uint32_t* r, uint32_t addr) {
    asm volatile("ldmatrix.sync.aligned.m8n8.x4.shared.b16 {%0,%1,%2,%3}, [%4];"
        : "=r"(r[0]), "=r"(r[1]), "=r"(r[2]), "=r"(r[3]) : "r"(addr));
}
__device__ __forceinline__ void mma16816(float* c, const uint32_t* a, const uint32_t* b) {
    asm volatile("mma.sync.aligned.m16n8k16.row.col.f32.bf16.bf16.f32 "
        "{%0,%1,%2,%3}, {%4,%5,%6,%7}, {%8,%9}, {%0,%1,%2,%3};"
        : "+f"(c[0]), "+f"(c[1]), "+f"(c[2]), "+f"(c[3])
        : "r"(a[0]), "r"(a[1]), "r"(a[2]), "r"(a[3]), "r"(b[0]), "r"(b[1]));
}

// =====================================================================
// conversion kernels: fp32 -> (hi, lo) bf16 split, pre-swizzled tiles
// =====================================================================
__device__ __forceinline__ void split4(const float4& v,
                                       unsigned long long& hh, unsigned long long& ll) {
    float f[4] = {v.x, v.y, v.z, v.w};
    unsigned long long h = 0, l = 0;
    #pragma unroll
    for (int i = 0; i < 4; i++) {
        __nv_bfloat16 hb = __float2bfloat16(f[i]);
        float hf = __bfloat162float(hb);
        __nv_bfloat16 lb = __float2bfloat16(f[i] - hf);
        h |= ((unsigned long long)__bfloat16_as_ushort(hb)) << (16 * i);
        l |= ((unsigned long long)__bfloat16_as_ushort(lb)) << (16 * i);
    }
    hh = h; ll = l;
}

__global__ void __launch_bounds__(256) convert_x_kernel(const float* __restrict__ x) {
    int gid = blockIdx.x * 256 + threadIdx.x;
    int m  = gid >> 8;
    int k4 = gid & 255;
    float4 v = *(const float4*)(x + (size_t)m * KK + (k4 << 2));
    unsigned long long hh, ll;
    split4(v, hh, ll);
    int mt = m >> 7, r = m & 127;
    int k = k4 << 2, kc = k >> 6, c = k & 63;
    uint32_t boff = r * 128 + c * 2;
    uint32_t sw = boff ^ ((boff >> 3) & 0x70);
    size_t tb = ((size_t)(mt * 16 + kc)) << 14;
    *(unsigned long long*)(g_xh + tb + sw) = hh;
    *(unsigned long long*)(g_xl + tb + sw) = ll;
}

__global__ void __launch_bounds__(256) convert_w_kernel(
    const float* __restrict__ Wi, const float* __restrict__ Wf,
    const float* __restrict__ Wh) {
    int gid = blockIdx.x * 256 + threadIdx.x;   // 3*1024*256 threads
    int mat = gid >> 18;
    int rem = gid & 262143;
    int d  = rem >> 8;
    int k4 = rem & 255;
    const float* W = (mat == 0) ? Wi : ((mat == 1) ? Wf : Wh);
    float4 v = *(const float4*)(W + (size_t)d * KK + (k4 << 2));
    unsigned long long hh, ll;
    split4(v, hh, ll);
    int nt = d >> 6;
    int r  = ((d >> 3) & 7) * 24 + mat * 8 + (d & 7);   // 8-feature interleave
    int k = k4 << 2, kc = k >> 6, c = k & 63;
    uint32_t boff = r * 128 + c * 2;
    uint32_t sw = boff ^ ((boff >> 3) & 0x70);
    size_t tb = (size_t)(nt * 16 + kc) * 24576;
    *(unsigned long long*)(g_wh + tb + sw) = hh;
    *(unsigned long long*)(g_wl + tb + sw) = ll;
}

// =====================================================================
// HMMA GEMM: CTA 128(M) x 192(N), K chunk 64, 2-stage pipeline with a
// DEDICATED PRODUCER WARP (warp 8). Compute warps (0-7) wait per-warp on
// "full" mbarriers and arrive on "empty" mbarriers -- no __syncthreads in
// the mainloop, so the tensor pipe never drains at chunk boundaries.
// =====================================================================
#define STG_BYTES 81920
#define OFF_AH 0
#define OFF_AL 16384
#define OFF_BH 32768
#define OFF_BL 57344
#define SMEM_TILES 1024
// ctrl layout: full barriers at sb+0, sb+8; empty barriers at sb+16, sb+24

__global__ void __launch_bounds__(288, 1)
gemm_kernel(const float* __restrict__ pbi, const float* __restrict__ pbf,
            const float* __restrict__ pbh) {
    extern __shared__ __align__(1024) unsigned char smem[];
    uint32_t sb = smem_to_u32(smem);
    const int tid = threadIdx.x;
    const int wid = tid >> 5, lane = tid & 31;
    const int nt = blockIdx.x;          // 0..15
    const int bt = blockIdx.y;          // 0..255

    if (tid == 0) {
        MBARRIER_INIT(sb + 0,  1);      // full s0
        MBARRIER_INIT(sb + 8,  1);      // full s1
        MBARRIER_INIT(sb + 16, 8);      // empty s0 (8 compute-warp arrives)
        MBARRIER_INIT(sb + 24, 8);      // empty s1
        FENCE_PROXY_ASYNC();
    }
    __syncthreads();

    if (wid == 8) {
        // ---------------- producer warp ----------------
        if (lane == 0) {
            #pragma unroll 1
            for (int c = 0; c < 16; c++) {
                const int s = c & 1;
                const uint32_t eph = (uint32_t)(((c >> 1) & 1) ^ 1);
                MBARRIER_WAIT_PARITY_RELAXED(sb + 16 + s * 8, eph);
                uint32_t fb = sb + s * 8;
                uint32_t dst = sb + SMEM_TILES + s * STG_BYTES;
                const unsigned char* ah = g_xh + (((size_t)(bt * 16 + c)) << 14);
                const unsigned char* al = g_xl + (((size_t)(bt * 16 + c)) << 14);
                const unsigned char* bh_ = g_wh + (size_t)(nt * 16 + c) * 24576;
                const unsigned char* bl_ = g_wl + (size_t)(nt * 16 + c) * 24576;
                MBARRIER_EXPECT_TX(fb, STG_BYTES);
                BULK_G2S(dst + OFF_AH, ah, 16384, fb);
                BULK_G2S(dst + OFF_AL, al, 16384, fb);
                BULK_G2S(dst + OFF_BH, bh_, 24576, fb);
                BULK_G2S(dst + OFF_BL, bl_, 24576, fb);
            }
        }
    } else {
        // ---------------- compute warps ----------------
        const int warpM = wid & 1;          // 0..1  (64 rows each)
        const int warpN = wid >> 1;         // 0..3  (48 N-rows each)
        const int g = lane >> 3;            // 0..3 ldmatrix lane-group
        const uint32_t xorv = (uint32_t)((lane & 7) << 4);
        uint32_t aoff[4], boff[3];
        #pragma unroll
        for (int mt = 0; mt < 4; mt++) {
            int row = warpM * 64 + mt * 16 + (g & 1) * 8 + (lane & 7);
            aoff[mt] = (uint32_t)(row * 128);
        }
        const uint32_t acol16 = (uint32_t)((g >> 1) * 16);
        #pragma unroll
        for (int p = 0; p < 3; p++) {
            int row = warpN * 48 + p * 16 + (g >> 1) * 8 + (lane & 7);
            boff[p] = (uint32_t)(row * 128);
        }
        const uint32_t bcol16 = (uint32_t)((g & 1) * 16);

        float acc[4][6][4];
        #pragma unroll
        for (int mt = 0; mt < 4; mt++)
            #pragma unroll
            for (int n8 = 0; n8 < 6; n8++)
                #pragma unroll
                for (int e = 0; e < 4; e++)
                    acc[mt][n8][e] = 0.0f;

        #pragma unroll 1
        for (int c = 0; c < 16; c++) {
            const int s = c & 1;
            const uint32_t ph = (uint32_t)((c >> 1) & 1);
            MBARRIER_WAIT_PARITY(sb + s * 8, ph);
            const uint32_t st = sb + SMEM_TILES + s * STG_BYTES;

            #pragma unroll
            for (int ks = 0; ks < 4; ks++) {
                const uint32_t ca = (uint32_t)(ks * 32);
                const uint32_t cswA = (ca + acol16) ^ xorv;
                const uint32_t cswB = (ca + bcol16) ^ xorv;
                uint32_t Ah[4][4], Al[4][4], Bh[3][4], Bl[3][4];
                #pragma unroll
                for (int mt = 0; mt < 4; mt++) {
                    ldsm4(Ah[mt], st + OFF_AH + aoff[mt] + cswA);
                    ldsm4(Al[mt], st + OFF_AL + aoff[mt] + cswA);
                }
                #pragma unroll
                for (int p = 0; p < 3; p++) {
                    ldsm4(Bh[p], st + OFF_BH + boff[p] + cswB);
                    ldsm4(Bl[p], st + OFF_BL + boff[p] + cswB);
                }
                #pragma unroll
                for (int mt = 0; mt < 4; mt++)
                    #pragma unroll
                    for (int n8 = 0; n8 < 6; n8++)
                        mma16816(acc[mt][n8], Ah[mt], &Bh[n8 >> 1][(n8 & 1) * 2]);
                #pragma unroll
                for (int mt = 0; mt < 4; mt++)
                    #pragma unroll
                    for (int n8 = 0; n8 < 6; n8++)
                        mma16816(acc[mt][n8], Al[mt], &Bh[n8 >> 1][(n8 & 1) * 2]);
                #pragma unroll
                for (int mt = 0; mt < 4; mt++)
                    #pragma unroll
                    for (int n8 = 0; n8 < 6; n8++)
                        mma16816(acc[mt][n8], Ah[mt], &Bl[n8 >> 1][(n8 & 1) * 2]);
            }
            // all ldsm results consumed by the MMAs above -> safe to release
            if (lane == 0) MBARRIER_ARRIVE(sb + 16 + s * 8);
        }

        // ---------------- fused gate epilogue ----------------
        #pragma unroll
        for (int gg = 0; gg < 2; gg++) {
            const int d0 = nt * 64 + (warpN * 2 + gg) * 8 + (lane & 3) * 2;
            const float bi0 = pbi[d0], bi1 = pbi[d0 + 1];
            const float bf0 = pbf[d0], bf1 = pbf[d0 + 1];
            const float bh0 = pbh[d0], bh1 = pbh[d0 + 1];
            #pragma unroll
            for (int mt = 0; mt < 4; mt++) {
                const int mrow0 = bt * 128 + warpM * 64 + mt * 16 + (lane >> 2);
                const float* zi = acc[mt][3 * gg + 0];
                const float* zf = acc[mt][3 * gg + 1];
                const float* zh = acc[mt][3 * gg + 2];
                #pragma unroll
                for (int e = 0; e < 2; e++) {
                    const int m = mrow0 + e * 8;
                    const int b = m >> 12;
                    float z_i0 = zi[2 * e] + bi0, z_i1 = zi[2 * e + 1] + bi1;
                    float z_f0 = zf[2 * e] + bf0, z_f1 = zf[2 * e + 1] + bf1;
                    float z_h0 = zh[2 * e] + bh0, z_h1 = zh[2 * e + 1] + bh1;
                    float df0 = sp(-z_f0) - sp(-z_i0);
                    float df1 = sp(-z_f1) - sp(-z_i1);
                    float lf0 = -sp(df0), lf1 = -sp(df1);
                    float lv0 = -sp(-df0) + log_g(z_h0);
                    float lv1 = -sp(-df1) + log_g(z_h1);
                    *(float2*)(g_logf + (size_t)m * DD + d0) = make_float2(lf0, lf1);
                    *(float2*)(g_lv + (size_t)(m + b + 1) * DD + d0) = make_float2(lv0, lv1);
                }
            }
        }
    }

    __syncthreads();
    if (tid == 0) {
        MBARRIER_INVAL(sb + 0);
        MBARRIER_INVAL(sb + 8);
        MBARRIER_INVAL(sb + 16);
        MBARRIER_INVAL(sb + 24);
    }
}

// =====================================================================
// log_values[:,0,:] = log_g(h_0)
// =====================================================================
__global__ void h0_kernel(const float* __restrict__ h0) {
    int i = blockIdx.x * 256 + threadIdx.x;
    int b = i >> 10;
    int d = i & (DD - 1);
    g_lv[(size_t)b * TP1 * DD + d] = log_g(h0[i]);
}

// =====================================================================
// a_star: feature-dim cumsum of log_f, shifted one row in time
// =====================================================================
__global__ void __launch_bounds__(256) cumsum_kernel() {
    int r = blockIdx.x;              // 0 .. B*TP1-1
    int b = r / TP1;
    int t = r - b * TP1;
    int tid = threadIdx.x;
    float4* dst = (float4*)(g_as + (size_t)r * DD);

    if (t == 0) {
        dst[tid] = make_float4(0.f, 0.f, 0.f, 0.f);
        return;
    }
    const float4* src = (const float4*)(g_logf + (size_t)(b * TT + t - 1) * DD);
    float4 v = src[tid];
    v.y += v.x; v.z += v.y; v.w += v.z;
    float tsum = v.w;

    int lane = tid & 31, warp = tid >> 5;
    #pragma unroll
    for (int off = 1; off < 32; off <<= 1) {
        float n = __shfl_up_sync(0xffffffffu, tsum, off);
        if (lane >= off) tsum += n;
    }
    __shared__ float wsum[8];
    if (lane == 31) wsum[warp] = tsum;
    __syncthreads();
    float prev = tsum - v.w;
    for (int w = 0; w < warp; w++) prev += wsum[w];
    v.x += prev; v.y += prev; v.z += prev; v.w += prev;
    dst[tid] = v;
}

// =====================================================================
// chunked logcumsumexp over time (3 passes, fully parallel)
// =====================================================================
__global__ void __launch_bounds__(256) scan_a_kernel() {
    int gid = blockIdx.x * 256 + threadIdx.x;   // < CH*BD
    int c  = gid >> 13;                          // /8192
    int bd = gid & (BD - 1);
    int b = bd >> 10, d = bd & (DD - 1);
    int t0 = c * CS;
    int t1 = t0 + CS; if (t1 > TP1) t1 = TP1;
    size_t base = (size_t)b * TP1 * DD + d;

    float m = -INFINITY, s = 0.0f;
    for (int t = t0; t < t1; t++) {
        size_t idx = base + (size_t)t * DD;
        float v  = g_lv[idx] - g_as[idx];
        float mn = fmaxf(m, v);
        s = s * expf(m - mn) + expf(v - mn);
        m = mn;
    }
    g_cm[gid] = m;
    g_cs[gid] = s;
}

__global__ void __launch_bounds__(256) scan_b_kernel() {
    int bd = blockIdx.x * 256 + threadIdx.x;    // < BD
    float M = -INFINITY, S = 0.0f;
    #pragma unroll 1
    for (int c = 0; c < CH; c++) {
        int i = c * BD + bd;
        g_pm[i] = M;
        g_ps[i] = S;
        float m = g_cm[i], s = g_cs[i];
        float mn = fmaxf(M, m);
        S = S * expf(M - mn) + s * expf(m - mn);
        M = mn;
    }
}

__global__ void __launch_bounds__(256) scan_c_kernel(float* __restrict__ out) {
    int gid = blockIdx.x * 256 + threadIdx.x;   // < CH*BD
    int c  = gid >> 13;
    int bd = gid & (BD - 1);
    int b = bd >> 10, d = bd & (DD - 1);
    int t0 = c * CS;
    int t1 = t0 + CS; if (t1 > TP1) t1 = TP1;
    size_t base = (size_t)b * TP1 * DD + d;

    float m = g_pm[gid];
    float s = g_ps[gid];
    for (int t = t0; t < t1; t++) {
        size_t idx = base + (size_t)t * DD;
        float a  = g_as[idx];
        float v  = g_lv[idx] - a;
        float mn = fmaxf(m, v);
        s = s * expf(m - mn) + expf(v - mn);
        m = mn;
        out[idx] = expf(a + m + logf(s));
    }
}

// =====================================================================
extern "C" void kernel_launch(void* const* d_in, const int* in_sizes, int n_in,
                              void* d_out, int out_size)
{
    const float* x  = (const float*)d_in[0];
    const float* h0 = (const float*)d_in[1];
    const float* Wi = (const float*)d_in[2];
    const float* bi = (const float*)d_in[3];
    const float* Wf = (const float*)d_in[4];
    const float* bf = (const float*)d_in[5];
    const float* Wh = (const float*)d_in[6];
    const float* bh = (const float*)d_in[7];
    float* out = (float*)d_out;
    (void)in_sizes; (void)n_in; (void)out_size;

    const int smem_bytes = SMEM_TILES + 2 * STG_BYTES;   // 164864
    cudaFuncSetAttribute(gemm_kernel, cudaFuncAttributeMaxDynamicSharedMemorySize, smem_bytes);

    convert_x_kernel<<<MM, 256>>>(x);
    convert_w_kernel<<<3072, 256>>>(Wi, Wf, Wh);
    h0_kernel<<<(BB * DD) / 256, 256>>>(h0);
    gemm_kernel<<<dim3(16, 256), 288, smem_bytes>>>(bi, bf, bh);
    cumsum_kernel<<<BB * TP1, 256>>>();
    scan_a_kernel<<<(CH * BD) / 256, 256>>>();
    scan_b_kernel<<<BD / 256, 256>>>();
    scan_c_kernel<<<(CH * BD) / 256, 256>>>(out);
}